// round 3
// baseline (speedup 1.0000x reference)
#include <cuda_runtime.h>
#include <math.h>

// Problem constants (hardcoded per reference setup_inputs)
#define BB 8
#define NN 4096
#define CC 256
#define HN 8
#define DH 32

// kv scratch: [b][h][e][d]  (e = v-channel, d = k-channel) -> 8*8*32*32 floats
__device__ float g_kv[BB * HN * DH * DH];

// ---------------- helpers ----------------

__device__ __forceinline__ float2 ffma2(float2 a, float2 b, float2 c) {
    union U { float2 f; unsigned long long u; };
    U A, B_, C_, D;
    A.f = a; B_.f = b; C_.f = c;
    asm("fma.rn.f32x2 %0, %1, %2, %3;" : "=l"(D.u) : "l"(A.u), "l"(B_.u), "l"(C_.u));
    return D.f;
}

__device__ __forceinline__ float leaky1(float x) {
    // leaky_relu(0.1): for x>=0 max(x,0.1x)=x; for x<0 max(x,0.1x)=0.1x
    return fmaxf(x, 0.1f * x);
}

__device__ __forceinline__ float4 prep4(float4 a, float4 p, float4 rs) {
    float4 r;
    r.x = leaky1(a.x + p.x) * rs.x;
    r.y = leaky1(a.y + p.y) * rs.y;
    r.z = leaky1(a.z + p.z) * rs.z;
    r.w = leaky1(a.w + p.w) * rs.w;
    return r;
}

__device__ __forceinline__ float dot4(float4 a, float4 b) {
    return a.x * b.x + a.y * b.y + a.z * b.z + a.w * b.w;
}

__device__ __forceinline__ float4 cube4(float4 a) {
    float4 r;
    r.x = a.x * a.x * a.x;
    r.y = a.y * a.y * a.y;
    r.z = a.z * a.z * a.z;
    r.w = a.w * a.w * a.w;
    return r;
}

__device__ __forceinline__ float4 mul4s(float4 a, float s) {
    float4 r; r.x = a.x * s; r.y = a.y * s; r.z = a.z * s; r.w = a.w * s; return r;
}

__device__ __forceinline__ float4 rsoft4(float4 s) {
    // 1 / softplus(s)
    float4 r;
    r.x = 1.0f / log1pf(expf(s.x));
    r.y = 1.0f / log1pf(expf(s.y));
    r.z = 1.0f / log1pf(expf(s.z));
    r.w = 1.0f / log1pf(expf(s.w));
    return r;
}

// ---------------- kernel 0: zero kv scratch ----------------

__global__ void zero_kv_kernel() {
    int i = blockIdx.x * blockDim.x + threadIdx.x;   // 64*256 = 16384 float4 = 65536 floats
    reinterpret_cast<float4*>(g_kv)[i] = make_float4(0.f, 0.f, 0.f, 0.f);
}

// ---------------- kernel 1: fused k-feature + kv accumulation ----------------
// grid (N/128, B), 256 threads (8 warps). Warp w == head w.
// Each group of 8 rows: one row per warp computes the focused k feature into
// shared, then every warp accumulates its head's 32x32 outer-product partials
// in registers. Block partials are atomically added into g_kv.

__global__ void __launch_bounds__(256) kv_kernel(
    const float* __restrict__ k, const float* __restrict__ v,
    const float* __restrict__ pe2, const float* __restrict__ scale)
{
    __shared__ float ks[8 * 256];
    __shared__ float vsm[8 * 256];

    const int tid = threadIdx.x;
    const int w = tid >> 5;
    const int lane = tid & 31;
    const int b = blockIdx.y;
    const int n0 = blockIdx.x * 128;

    const float4* sc4 = reinterpret_cast<const float4*>(scale);
    const float4 rs0 = rsoft4(sc4[lane]);
    const float4 rs1 = rsoft4(sc4[32 + lane]);

    float2 acc[16];
#pragma unroll
    for (int j = 0; j < 16; j++) acc[j] = make_float2(0.f, 0.f);

    for (int g = 0; g < 16; g++) {
        const int row = n0 + g * 8 + w;
        const float4* kg = reinterpret_cast<const float4*>(k + ((size_t)b * NN + row) * CC);
        const float4* vg = reinterpret_cast<const float4*>(v + ((size_t)b * NN + row) * CC);
        const float4* pg = reinterpret_cast<const float4*>(pe2 + (size_t)row * CC);

        float4 a0 = kg[lane], a1 = kg[32 + lane];
        float4 v0 = vg[lane], v1 = vg[32 + lane];
        float4 p0 = pg[lane], p1 = pg[32 + lane];

        float4 t0 = prep4(a0, p0, rs0);
        float4 t1 = prep4(a1, p1, rs1);
        float s2 = dot4(t0, t0) + dot4(t1, t1);
        float4 u0 = cube4(t0), u1 = cube4(t1);
        float s6 = dot4(u0, u0) + dot4(u1, u1);
#pragma unroll
        for (int m = 16; m; m >>= 1) {
            s2 += __shfl_xor_sync(0xffffffffu, s2, m);
            s6 += __shfl_xor_sync(0xffffffffu, s6, m);
        }
        const float f = (s6 > 0.f) ? sqrtf(s2 / s6) : 0.f;

        reinterpret_cast<float4*>(ks)[w * 64 + lane]      = mul4s(u0, f);
        reinterpret_cast<float4*>(ks)[w * 64 + 32 + lane] = mul4s(u1, f);
        reinterpret_cast<float4*>(vsm)[w * 64 + lane]      = v0;
        reinterpret_cast<float4*>(vsm)[w * 64 + 32 + lane] = v1;
        __syncthreads();

#pragma unroll
        for (int r = 0; r < 8; r++) {
            const float kd = ks[r * 256 + w * 32 + lane];        // d = lane
            const float2 k2 = make_float2(kd, kd);
            const float4* vp = reinterpret_cast<const float4*>(&vsm[r * 256 + w * 32]);
#pragma unroll
            for (int j = 0; j < 8; j++) {
                float4 vv = vp[j];                               // e = 4j..4j+3
                acc[2 * j]     = ffma2(k2, make_float2(vv.x, vv.y), acc[2 * j]);
                acc[2 * j + 1] = ffma2(k2, make_float2(vv.z, vv.w), acc[2 * j + 1]);
            }
        }
        __syncthreads();
    }

    float* base = g_kv + ((size_t)b * HN + w) * (DH * DH);       // [e][d]
#pragma unroll
    for (int j = 0; j < 16; j++) {
        atomicAdd(base + (2 * j) * DH + lane,     acc[j].x);
        atomicAdd(base + (2 * j + 1) * DH + lane, acc[j].y);
    }
}

// ---------------- kernel 2: q-feature + x = qf@kv + leaky(v@W^T + b) ----------------
// grid (N/32, B), 256 threads (8 warps). Tile = 32 rows (n) x 256 channels.
// Shared: padded (stride 260) qf/v row tiles (conflict-free col reads), staged
// kv[b] and W (broadcast LDS). Warp w == head w; lane == local n. Output writes
// coalesced along n.

#define ROWPAD 260
#define SMEM_FLOATS (2 * 32 * ROWPAD + HN * DH * DH + DH * DH + DH)
#define SMEM_BYTES (SMEM_FLOATS * 4)

__global__ void __launch_bounds__(256) out_kernel(
    const float* __restrict__ q, const float* __restrict__ v,
    const float* __restrict__ pe1, const float* __restrict__ scale,
    const float* __restrict__ wconv, const float* __restrict__ bconv,
    float* __restrict__ out)
{
    extern __shared__ float sm[];
    float* sqf = sm;                       // 32*260
    float* svs = sm + 32 * ROWPAD;         // 32*260
    float* skv = sm + 2 * 32 * ROWPAD;     // 8192  [h][e][d]
    float* sW  = skv + HN * DH * DH;       // 1024  [o][d]
    float* sb  = sW + DH * DH;             // 32

    const int tid = threadIdx.x;
    const int w = tid >> 5;
    const int lane = tid & 31;
    const int b = blockIdx.y;
    const int n0 = blockIdx.x * 32;

    // stage W, bias, kv[b]
    reinterpret_cast<float4*>(sW)[tid] = reinterpret_cast<const float4*>(wconv)[tid];
    if (tid < 32) sb[tid] = bconv[tid];
    {
        const float4* kvg = reinterpret_cast<const float4*>(g_kv + (size_t)b * HN * DH * DH);
        float4* skv4 = reinterpret_cast<float4*>(skv);
#pragma unroll
        for (int i = 0; i < 8; i++) skv4[i * 256 + tid] = kvg[i * 256 + tid];
    }

    const float4* sc4 = reinterpret_cast<const float4*>(scale);
    const float4 rs0 = rsoft4(sc4[lane]);
    const float4 rs1 = rsoft4(sc4[32 + lane]);

    // phase 1: q features + v staging (warp w handles rows w*4 .. w*4+3)
#pragma unroll
    for (int i = 0; i < 4; i++) {
        const int rl = w * 4 + i;
        const int row = n0 + rl;
        const float4* qg = reinterpret_cast<const float4*>(q + ((size_t)b * NN + row) * CC);
        const float4* vg = reinterpret_cast<const float4*>(v + ((size_t)b * NN + row) * CC);
        const float4* pg = reinterpret_cast<const float4*>(pe1 + (size_t)row * CC);

        float4 a0 = qg[lane], a1 = qg[32 + lane];
        float4 v0 = vg[lane], v1 = vg[32 + lane];
        float4 p0 = pg[lane], p1 = pg[32 + lane];

        float4 t0 = prep4(a0, p0, rs0);
        float4 t1 = prep4(a1, p1, rs1);
        float s2 = dot4(t0, t0) + dot4(t1, t1);
        float4 u0 = cube4(t0), u1 = cube4(t1);
        float s6 = dot4(u0, u0) + dot4(u1, u1);
#pragma unroll
        for (int m = 16; m; m >>= 1) {
            s2 += __shfl_xor_sync(0xffffffffu, s2, m);
            s6 += __shfl_xor_sync(0xffffffffu, s6, m);
        }
        // fold the 1/N of kv normalization into the q factor
        const float f = (s6 > 0.f) ? sqrtf(s2 / s6) * (1.0f / (float)NN) : 0.f;

        float* qrow = sqf + rl * ROWPAD;
        *reinterpret_cast<float4*>(qrow + lane * 4)       = mul4s(u0, f);
        *reinterpret_cast<float4*>(qrow + 128 + lane * 4) = mul4s(u1, f);
        float* vrow = svs + rl * ROWPAD;
        *reinterpret_cast<float4*>(vrow + lane * 4)       = v0;
        *reinterpret_cast<float4*>(vrow + 128 + lane * 4) = v1;
    }
    __syncthreads();

    // phase 2: per-lane row (n = n0+lane), per-warp head (h = w)
    float2 q2[16], v2[16];
    {
        const float4* qp = reinterpret_cast<const float4*>(sqf + lane * ROWPAD + w * DH);
        const float4* vp = reinterpret_cast<const float4*>(svs + lane * ROWPAD + w * DH);
#pragma unroll
        for (int j = 0; j < 8; j++) {
            float4 t = qp[j];
            q2[2 * j]     = make_float2(t.x, t.y);
            q2[2 * j + 1] = make_float2(t.z, t.w);
            float4 s = vp[j];
            v2[2 * j]     = make_float2(s.x, s.y);
            v2[2 * j + 1] = make_float2(s.z, s.w);
        }
    }

    const int n = n0 + lane;
    float* outb = out + ((size_t)b * CC + w * DH) * NN + n;

#pragma unroll 4
    for (int e = 0; e < DH; e++) {
        const float4* kp = reinterpret_cast<const float4*>(skv + w * (DH * DH) + e * DH);
        const float4* wp = reinterpret_cast<const float4*>(sW + e * DH);
        float2 ax0 = make_float2(0.f, 0.f), ax1 = make_float2(0.f, 0.f);
        float2 ac0 = make_float2(0.f, 0.f), ac1 = make_float2(0.f, 0.f);
#pragma unroll
        for (int j = 0; j < 4; j++) {
            float4 kd0 = kp[2 * j], kd1 = kp[2 * j + 1];
            float4 wd0 = wp[2 * j], wd1 = wp[2 * j + 1];
            ax0 = ffma2(q2[4 * j],     make_float2(kd0.x, kd0.y), ax0);
            ax1 = ffma2(q2[4 * j + 1], make_float2(kd0.z, kd0.w), ax1);
            ax0 = ffma2(q2[4 * j + 2], make_float2(kd1.x, kd1.y), ax0);
            ax1 = ffma2(q2[4 * j + 3], make_float2(kd1.z, kd1.w), ax1);
            ac0 = ffma2(v2[4 * j],     make_float2(wd0.x, wd0.y), ac0);
            ac1 = ffma2(v2[4 * j + 1], make_float2(wd0.z, wd0.w), ac1);
            ac0 = ffma2(v2[4 * j + 2], make_float2(wd1.x, wd1.y), ac0);
            ac1 = ffma2(v2[4 * j + 3], make_float2(wd1.z, wd1.w), ac1);
        }
        float xv = (ax0.x + ax0.y) + (ax1.x + ax1.y);
        float cv = (ac0.x + ac0.y) + (ac1.x + ac1.y) + sb[e];
        cv = leaky1(cv);
        outb[(size_t)e * NN] = xv + cv;
    }
}

// ---------------- launch ----------------

extern "C" void kernel_launch(void* const* d_in, const int* in_sizes, int n_in,
                              void* d_out, int out_size)
{
    (void)in_sizes; (void)n_in; (void)out_size;
    const float* q     = (const float*)d_in[0];
    const float* k     = (const float*)d_in[1];
    const float* v     = (const float*)d_in[2];
    const float* pe1   = (const float*)d_in[3];
    const float* pe2   = (const float*)d_in[4];
    const float* scale = (const float*)d_in[5];
    const float* wconv = (const float*)d_in[6];
    const float* bconv = (const float*)d_in[7];
    float* out = (float*)d_out;

    cudaFuncSetAttribute(out_kernel, cudaFuncAttributeMaxDynamicSharedMemorySize, SMEM_BYTES);

    zero_kv_kernel<<<64, 256>>>();
    kv_kernel<<<dim3(NN / 128, BB), 256>>>(k, v, pe2, scale);
    out_kernel<<<dim3(NN / 32, BB), 256, SMEM_BYTES>>>(q, v, pe1, scale, wconv, bconv, out);
}

// round 4
// speedup vs baseline: 1.1278x; 1.1278x over previous
#include <cuda_runtime.h>
#include <math.h>

// Problem constants (per reference setup_inputs)
#define BB 8
#define NN 4096
#define CC 256
#define HN 8
#define DH 32

// kv scratch: [b][h][e][d] -> 8*8*32*32 floats, and precomputed 1/softplus(scale)
__device__ float g_kv[BB * HN * DH * DH];
__device__ float g_rscale[CC];

// ---------------- helpers ----------------

__device__ __forceinline__ float2 ffma2(float2 a, float2 b, float2 c) {
    union U { float2 f; unsigned long long u; };
    U A, B_, C_, D;
    A.f = a; B_.f = b; C_.f = c;
    asm("fma.rn.f32x2 %0, %1, %2, %3;" : "=l"(D.u) : "l"(A.u), "l"(B_.u), "l"(C_.u));
    return D.f;
}

__device__ __forceinline__ float leaky1(float x) {
    return fmaxf(x, 0.1f * x);
}

__device__ __forceinline__ float4 prep4(float4 a, float4 p, float4 rs) {
    float4 r;
    r.x = leaky1(a.x + p.x) * rs.x;
    r.y = leaky1(a.y + p.y) * rs.y;
    r.z = leaky1(a.z + p.z) * rs.z;
    r.w = leaky1(a.w + p.w) * rs.w;
    return r;
}

__device__ __forceinline__ float dot4(float4 a, float4 b) {
    return a.x * b.x + a.y * b.y + a.z * b.z + a.w * b.w;
}

__device__ __forceinline__ float4 cube4(float4 a) {
    float4 r;
    r.x = a.x * a.x * a.x;
    r.y = a.y * a.y * a.y;
    r.z = a.z * a.z * a.z;
    r.w = a.w * a.w * a.w;
    return r;
}

__device__ __forceinline__ float4 mul4s(float4 a, float s) {
    float4 r; r.x = a.x * s; r.y = a.y * s; r.z = a.z * s; r.w = a.w * s; return r;
}

// ---------------- kernel 0: zero kv scratch + precompute 1/softplus(scale) ----------------

__global__ void setup_kernel(const float* __restrict__ scale) {
    int i = blockIdx.x * blockDim.x + threadIdx.x;   // 64*256 = 16384 float4
    reinterpret_cast<float4*>(g_kv)[i] = make_float4(0.f, 0.f, 0.f, 0.f);
    if (blockIdx.x == 0) {
        float s = scale[threadIdx.x];
        g_rscale[threadIdx.x] = 1.0f / log1pf(expf(s));
    }
}

// ---------------- kernel 1: fused k-feature + kv accumulation ----------------
// grid (64, B) = 512 blocks, 256 threads (8 warps). Warp w == head w.
// 64 rows per block as 8 groups of 8 rows (one row per warp). Double-buffered
// smem staging; next group's global loads are issued right after the barrier
// and hidden under the current group's 128-FFMA2 accumulate.

__global__ void __launch_bounds__(256) kv_kernel(
    const float* __restrict__ k, const float* __restrict__ v,
    const float* __restrict__ pe2)
{
    __shared__ float ks[2][8 * 256];
    __shared__ float vsm[2][8 * 256];

    const int tid = threadIdx.x;
    const int w = tid >> 5;
    const int lane = tid & 31;
    const int b = blockIdx.y;
    const int n0 = blockIdx.x * 64;

    const float4* rsg = reinterpret_cast<const float4*>(g_rscale);
    const float4 rs0 = rsg[lane];
    const float4 rs1 = rsg[32 + lane];

    float2 acc[16];
#pragma unroll
    for (int j = 0; j < 16; j++) acc[j] = make_float2(0.f, 0.f);

    // preload group 0
    float4 ka0, ka1, va0, va1, pa0, pa1;
    {
        const int row = n0 + w;
        const float4* kg = reinterpret_cast<const float4*>(k + ((size_t)b * NN + row) * CC);
        const float4* vg = reinterpret_cast<const float4*>(v + ((size_t)b * NN + row) * CC);
        const float4* pg = reinterpret_cast<const float4*>(pe2 + (size_t)row * CC);
        ka0 = kg[lane]; ka1 = kg[32 + lane];
        va0 = vg[lane]; va1 = vg[32 + lane];
        pa0 = pg[lane]; pa1 = pg[32 + lane];
    }

#pragma unroll
    for (int g = 0; g < 8; g++) {
        const int buf = g & 1;

        // feature transform of current group (registers)
        float4 t0 = prep4(ka0, pa0, rs0);
        float4 t1 = prep4(ka1, pa1, rs1);
        float s2 = dot4(t0, t0) + dot4(t1, t1);
        float4 u0 = cube4(t0), u1 = cube4(t1);
        float s6 = dot4(u0, u0) + dot4(u1, u1);
#pragma unroll
        for (int m = 16; m; m >>= 1) {
            s2 += __shfl_xor_sync(0xffffffffu, s2, m);
            s6 += __shfl_xor_sync(0xffffffffu, s6, m);
        }
        const float f = (s6 > 0.f) ? sqrtf(s2 / s6) : 0.f;

        reinterpret_cast<float4*>(ks[buf])[w * 64 + lane]      = mul4s(u0, f);
        reinterpret_cast<float4*>(ks[buf])[w * 64 + 32 + lane] = mul4s(u1, f);
        reinterpret_cast<float4*>(vsm[buf])[w * 64 + lane]      = va0;
        reinterpret_cast<float4*>(vsm[buf])[w * 64 + 32 + lane] = va1;
        __syncthreads();

        // prefetch next group (hidden under the accumulate below)
        if (g < 7) {
            const int row = n0 + (g + 1) * 8 + w;
            const float4* kg = reinterpret_cast<const float4*>(k + ((size_t)b * NN + row) * CC);
            const float4* vg = reinterpret_cast<const float4*>(v + ((size_t)b * NN + row) * CC);
            const float4* pg = reinterpret_cast<const float4*>(pe2 + (size_t)row * CC);
            ka0 = kg[lane]; ka1 = kg[32 + lane];
            va0 = vg[lane]; va1 = vg[32 + lane];
            pa0 = pg[lane]; pa1 = pg[32 + lane];
        }

        // accumulate: thread owns d=lane for head w, all 32 e
#pragma unroll
        for (int r = 0; r < 8; r++) {
            const float kd = ks[buf][r * 256 + w * 32 + lane];
            const float2 k2 = make_float2(kd, kd);
            const float4* vp = reinterpret_cast<const float4*>(&vsm[buf][r * 256 + w * 32]);
#pragma unroll
            for (int j = 0; j < 8; j++) {
                float4 vv = vp[j];
                acc[2 * j]     = ffma2(k2, make_float2(vv.x, vv.y), acc[2 * j]);
                acc[2 * j + 1] = ffma2(k2, make_float2(vv.z, vv.w), acc[2 * j + 1]);
            }
        }
        // no second barrier needed: buffer buf is next rewritten only after
        // the following barrier, by which time all reads of it are done.
    }

    float* base = g_kv + ((size_t)b * HN + w) * (DH * DH);       // [e][d]
#pragma unroll
    for (int j = 0; j < 16; j++) {
        atomicAdd(base + (2 * j) * DH + lane,     acc[j].x);
        atomicAdd(base + (2 * j + 1) * DH + lane, acc[j].y);
    }
}

// ---------------- kernel 2: q-feature + x = qf@kv + leaky(v@W^T + b) ----------------
// Persistent-ish: grid (32, 8) = 256 blocks = exactly 2 resident CTAs per SM.
// Each block processes 4 tiles of 32 rows. Co-resident blocks overlap each
// other's load and compute phases; no wave transitions.

#define ROWPAD 260
#define SMEM_FLOATS (2 * 32 * ROWPAD + HN * DH * DH + DH * DH + DH)
#define SMEM_BYTES (SMEM_FLOATS * 4)

__global__ void __launch_bounds__(256, 2) out_kernel(
    const float* __restrict__ q, const float* __restrict__ v,
    const float* __restrict__ pe1,
    const float* __restrict__ wconv, const float* __restrict__ bconv,
    float* __restrict__ out)
{
    extern __shared__ float sm[];
    float* sqf = sm;                       // 32*260
    float* svs = sm + 32 * ROWPAD;         // 32*260
    float* skv = sm + 2 * 32 * ROWPAD;     // 8192  [h][e][d]
    float* sW  = skv + HN * DH * DH;       // 1024  [o][d]
    float* sb  = sW + DH * DH;             // 32

    const int tid = threadIdx.x;
    const int w = tid >> 5;
    const int lane = tid & 31;
    const int b = blockIdx.y;

    // stage W, bias, kv[b] once per block
    reinterpret_cast<float4*>(sW)[tid] = reinterpret_cast<const float4*>(wconv)[tid];
    if (tid < 32) sb[tid] = bconv[tid];
    {
        const float4* kvg = reinterpret_cast<const float4*>(g_kv + (size_t)b * HN * DH * DH);
        float4* skv4 = reinterpret_cast<float4*>(skv);
#pragma unroll
        for (int i = 0; i < 8; i++) skv4[i * 256 + tid] = kvg[i * 256 + tid];
    }

    const float4* rsg = reinterpret_cast<const float4*>(g_rscale);
    const float4 rs0 = rsg[lane];
    const float4 rs1 = rsg[32 + lane];

    for (int it = 0; it < 4; it++) {
        const int n0 = (blockIdx.x * 4 + it) * 32;

        __syncthreads();   // previous tile's e-loop readers done before rewriting smem

        // phase 1: q features + v staging (warp w handles rows w*4 .. w*4+3)
#pragma unroll
        for (int i = 0; i < 4; i++) {
            const int rl = w * 4 + i;
            const int row = n0 + rl;
            const float4* qg = reinterpret_cast<const float4*>(q + ((size_t)b * NN + row) * CC);
            const float4* vg = reinterpret_cast<const float4*>(v + ((size_t)b * NN + row) * CC);
            const float4* pg = reinterpret_cast<const float4*>(pe1 + (size_t)row * CC);

            float4 a0 = qg[lane], a1 = qg[32 + lane];
            float4 v0 = vg[lane], v1 = vg[32 + lane];
            float4 p0 = pg[lane], p1 = pg[32 + lane];

            float4 t0 = prep4(a0, p0, rs0);
            float4 t1 = prep4(a1, p1, rs1);
            float s2 = dot4(t0, t0) + dot4(t1, t1);
            float4 u0 = cube4(t0), u1 = cube4(t1);
            float s6 = dot4(u0, u0) + dot4(u1, u1);
#pragma unroll
            for (int m = 16; m; m >>= 1) {
                s2 += __shfl_xor_sync(0xffffffffu, s2, m);
                s6 += __shfl_xor_sync(0xffffffffu, s6, m);
            }
            // fold the 1/N of kv normalization into the q factor
            const float f = (s6 > 0.f) ? sqrtf(s2 / s6) * (1.0f / (float)NN) : 0.f;

            float* qrow = sqf + rl * ROWPAD;
            *reinterpret_cast<float4*>(qrow + lane * 4)       = mul4s(u0, f);
            *reinterpret_cast<float4*>(qrow + 128 + lane * 4) = mul4s(u1, f);
            float* vrow = svs + rl * ROWPAD;
            *reinterpret_cast<float4*>(vrow + lane * 4)       = v0;
            *reinterpret_cast<float4*>(vrow + 128 + lane * 4) = v1;
        }
        __syncthreads();

        // phase 2: per-lane row (n = n0+lane), per-warp head (h = w)
        float2 q2[16], v2[16];
        {
            const float4* qp = reinterpret_cast<const float4*>(sqf + lane * ROWPAD + w * DH);
            const float4* vp = reinterpret_cast<const float4*>(svs + lane * ROWPAD + w * DH);
#pragma unroll
            for (int j = 0; j < 8; j++) {
                float4 t = qp[j];
                q2[2 * j]     = make_float2(t.x, t.y);
                q2[2 * j + 1] = make_float2(t.z, t.w);
                float4 s = vp[j];
                v2[2 * j]     = make_float2(s.x, s.y);
                v2[2 * j + 1] = make_float2(s.z, s.w);
            }
        }

        const int n = n0 + lane;
        float* outb = out + ((size_t)b * CC + w * DH) * NN + n;

#pragma unroll 4
        for (int e = 0; e < DH; e++) {
            const float4* kp = reinterpret_cast<const float4*>(skv + w * (DH * DH) + e * DH);
            const float4* wp = reinterpret_cast<const float4*>(sW + e * DH);
            float2 ax0 = make_float2(0.f, 0.f), ax1 = make_float2(0.f, 0.f);
            float2 ac0 = make_float2(0.f, 0.f), ac1 = make_float2(0.f, 0.f);
#pragma unroll
            for (int j = 0; j < 4; j++) {
                float4 kd0 = kp[2 * j], kd1 = kp[2 * j + 1];
                float4 wd0 = wp[2 * j], wd1 = wp[2 * j + 1];
                ax0 = ffma2(q2[4 * j],     make_float2(kd0.x, kd0.y), ax0);
                ax1 = ffma2(q2[4 * j + 1], make_float2(kd0.z, kd0.w), ax1);
                ax0 = ffma2(q2[4 * j + 2], make_float2(kd1.x, kd1.y), ax0);
                ax1 = ffma2(q2[4 * j + 3], make_float2(kd1.z, kd1.w), ax1);
                ac0 = ffma2(v2[4 * j],     make_float2(wd0.x, wd0.y), ac0);
                ac1 = ffma2(v2[4 * j + 1], make_float2(wd0.z, wd0.w), ac1);
                ac0 = ffma2(v2[4 * j + 2], make_float2(wd1.x, wd1.y), ac0);
                ac1 = ffma2(v2[4 * j + 3], make_float2(wd1.z, wd1.w), ac1);
            }
            float xv = (ax0.x + ax0.y) + (ax1.x + ax1.y);
            float cv = (ac0.x + ac0.y) + (ac1.x + ac1.y) + sb[e];
            cv = leaky1(cv);
            outb[(size_t)e * NN] = xv + cv;
        }
    }
}

// ---------------- launch ----------------

extern "C" void kernel_launch(void* const* d_in, const int* in_sizes, int n_in,
                              void* d_out, int out_size)
{
    (void)in_sizes; (void)n_in; (void)out_size;
    const float* q     = (const float*)d_in[0];
    const float* k     = (const float*)d_in[1];
    const float* v     = (const float*)d_in[2];
    const float* pe1   = (const float*)d_in[3];
    const float* pe2   = (const float*)d_in[4];
    const float* scale = (const float*)d_in[5];
    const float* wconv = (const float*)d_in[6];
    const float* bconv = (const float*)d_in[7];
    float* out = (float*)d_out;

    cudaFuncSetAttribute(out_kernel, cudaFuncAttributeMaxDynamicSharedMemorySize, SMEM_BYTES);

    setup_kernel<<<64, 256>>>(scale);
    kv_kernel<<<dim3(NN / 64, BB), 256>>>(k, v, pe2);
    out_kernel<<<dim3(NN / 128, BB), 256, SMEM_BYTES>>>(q, v, pe1, wconv, bconv, out);
}